// round 13
// baseline (speedup 1.0000x reference)
#include <cuda_runtime.h>

#define HID 24
#define TPB 32
#define WSTRIDE 218   // u64 stride per q-block (216 payload + 2 pad): q*1744B mod 128 = {0,80,32,112} -> conflict-free

typedef unsigned long long u64;

__device__ __forceinline__ u64 pack2(float x, float y) {
    u64 r; asm("mov.b64 %0, {%1, %2};" : "=l"(r) : "f"(x), "f"(y)); return r;
}
__device__ __forceinline__ void unpack2(u64 v, float &x, float &y) {
    asm("mov.b64 {%0, %1}, %2;" : "=f"(x), "=f"(y) : "l"(v));
}
__device__ __forceinline__ u64 ffma2(u64 a, u64 b, u64 c) {
    u64 d; asm("fma.rn.f32x2 %0, %1, %2, %3;" : "=l"(d) : "l"(a), "l"(b), "l"(c)); return d;
}
__device__ __forceinline__ u64 fadd2(u64 a, u64 b) {
    u64 d; asm("add.rn.f32x2 %0, %1, %2;" : "=l"(d) : "l"(a), "l"(b)); return d;
}
__device__ __forceinline__ float ex2a(float x) {
    float r; asm("ex2.approx.f32 %0, %1;" : "=f"(r) : "f"(x)); return r;
}
__device__ __forceinline__ float rcpa(float x) {
    float r; asm("rcp.approx.f32 %0, %1;" : "=f"(r) : "f"(x)); return r;
}
__device__ __forceinline__ float sig_f(float v) {
    return rcpa(1.0f + ex2a(v * -1.442695041f));
}
__device__ __forceinline__ float tanh_f(float v) {
    return fmaf(2.0f, rcpa(1.0f + ex2a(v * -2.885390082f)), -1.0f);
}

// Cohort = 4 lanes <-> 4 sequences. Lane q owns gate rows {r,z,n} x units
// [6q, 6q+6) and computes FULL k=24 matvec for all 4 cohort seqs (no k-split,
// no reduce). h gathered lazily per k-pair via shfl from the owning lane.
__global__ void __launch_bounds__(TPB, 8)
trendgru_kernel(const float* __restrict__ x,
                const float* __restrict__ W_ih,
                const float* __restrict__ b_ih,
                const float* __restrict__ W_hh,
                const float* __restrict__ b_hh,
                const float* __restrict__ fc_w,
                const float* __restrict__ fc_b,
                float* __restrict__ out,
                int B, int T)
{
    // sW[q*218 + j*24 + k] = pack2(W_hh[r0][k], W_hh[r0+1][k]),
    //  j = gate*3+p (gate 0=r,1=z,2=n), r0 = gate*24 + 6q + 2p, k = 0..23
    __shared__ __align__(16) u64 sW[4 * WSTRIDE];
    __shared__ __align__(16) ulonglong2 cRZ[4][6];  // (W_ih pair, b_ih+b_hh pair)
    __shared__ __align__(16) ulonglong2 cN[4][3];   // (W_ih_n pair, b_ih_n pair)
    __shared__ u64 cNH[4][3];                       // b_hh n pairs

    const int tid = threadIdx.x;
    for (int i = tid; i < 4 * 216; i += TPB) {
        int qq = i / 216, rem = i % 216;
        int j = rem / 24, k = rem % 24;
        int gate = j / 3, p = j % 3;
        int r0 = gate * 24 + 6 * qq + 2 * p;
        sW[qq * WSTRIDE + j * 24 + k] = pack2(W_hh[r0 * HID + k], W_hh[(r0 + 1) * HID + k]);
    }
    if (tid < 24) {
        int qq = tid / 6, j6 = tid % 6;
        int gate = j6 / 3, p = j6 % 3;
        int r0 = gate * 24 + 6 * qq + 2 * p;
        cRZ[qq][j6].x = pack2(W_ih[r0], W_ih[r0 + 1]);
        cRZ[qq][j6].y = pack2(b_ih[r0] + b_hh[r0], b_ih[r0 + 1] + b_hh[r0 + 1]);
    }
    if (tid < 12) {
        int qq = tid / 3, p = tid % 3;
        int r0 = 48 + 6 * qq + 2 * p;
        cN[qq][p].x = pack2(W_ih[r0], W_ih[r0 + 1]);
        cN[qq][p].y = pack2(b_ih[r0], b_ih[r0 + 1]);
        cNH[qq][p]  = pack2(b_hh[r0], b_hh[r0 + 1]);
    }
    __syncthreads();

    const int q    = tid & 3;
    const int cbase = tid & ~3;                    // cohort base lane
    const int sbase = (blockIdx.x * TPB + tid) >> 2 << 2;  // 4 seqs per cohort

    const ulonglong2* wq = reinterpret_cast<const ulonglong2*>(&sW[q * WSTRIDE]);
    const float* xb = x + (size_t)sbase * T;

    u64 hown[4][3];   // own h pairs (units 6q..6q+5) for seqs sbase..sbase+3
    #pragma unroll
    for (int m = 0; m < 4; m++)
        #pragma unroll
        for (int p = 0; p < 3; p++) hown[m][p] = 0ULL;

    const u64 SGN2 = 0x8000000080000000ULL;

    float xv[4];
    #pragma unroll
    for (int m = 0; m < 4; m++) xv[m] = __ldg(xb + (size_t)m * T);

    for (int t = 0; t < T; t++) {
        const int tn = (t + 1 < T) ? (t + 1) : t;
        float xnx[4];
        #pragma unroll
        for (int m = 0; m < 4; m++) xnx[m] = __ldg(xb + (size_t)m * T + tn);

        u64 x2[4];
        #pragma unroll
        for (int m = 0; m < 4; m++) x2[m] = pack2(xv[m], xv[m]);

        u64 acc[4][9];
        #pragma unroll
        for (int j6 = 0; j6 < 6; j6++) {          // r (0-2), z (3-5): fold x-proj + biases
            const ulonglong2 w = cRZ[q][j6];
            #pragma unroll
            for (int m = 0; m < 4; m++)
                acc[m][j6] = ffma2(w.x, x2[m], w.y);
        }
        #pragma unroll
        for (int p = 0; p < 3; p++) {             // hn: start from b_hh
            const u64 bv = cNH[q][p];
            #pragma unroll
            for (int m = 0; m < 4; m++) acc[m][6 + p] = bv;
        }

        // matvec over 12 global h-pairs; pair i owned by lane cbase + i/3
        #pragma unroll
        for (int i = 0; i < 12; i++) {
            const int src = cbase + (i / 3);
            u64 e0[4], e1[4];
            #pragma unroll
            for (int m = 0; m < 4; m++) {
                const u64 hv = __shfl_sync(0xFFFFFFFFu, hown[m][i % 3], src);
                float h0, h1; unpack2(hv, h0, h1);
                e0[m] = pack2(h0, h0);
                e1[m] = pack2(h1, h1);
            }
            #pragma unroll
            for (int j = 0; j < 9; j++) {
                const ulonglong2 w = wq[j * 12 + i];   // k = 2i (x), 2i+1 (y)
                #pragma unroll
                for (int m = 0; m < 4; m++) {
                    acc[m][j] = ffma2(w.x, e0[m], acc[m][j]);
                    acc[m][j] = ffma2(w.y, e1[m], acc[m][j]);
                }
            }
        }

        // gates + h update: own 3 pairs x 4 seqs
        #pragma unroll
        for (int m = 0; m < 4; m++) {
            #pragma unroll
            for (int p = 0; p < 3; p++) {
                float a0, a1, c0, c1;
                unpack2(acc[m][p], a0, a1);
                unpack2(acc[m][3 + p], c0, c1);
                const u64 r2 = pack2(sig_f(a0), sig_f(a1));
                const u64 z2 = pack2(sig_f(c0), sig_f(c1));
                const ulonglong2 wn = cN[q][p];
                const u64 xn = ffma2(wn.x, x2[m], wn.y);
                const u64 npre = ffma2(r2, acc[m][6 + p], xn);
                float n0, n1; unpack2(npre, n0, n1);
                const u64 n2 = pack2(tanh_f(n0), tanh_f(n1));
                // h = n + z*(h - n)
                hown[m][p] = ffma2(z2, fadd2(hown[m][p], n2 ^ SGN2), n2);
            }
        }

        #pragma unroll
        for (int m = 0; m < 4; m++) xv[m] = xnx[m];
    }

    // final fc: partials over own 6 units, reduce across the 4 cohort lanes
    float p0[4], p1[4];
    #pragma unroll
    for (int m = 0; m < 4; m++) { p0[m] = 0.f; p1[m] = 0.f; }
    #pragma unroll
    for (int p = 0; p < 3; p++) {
        const int k = 6 * q + 2 * p;
        const float w00 = __ldg(fc_w + k),      w01 = __ldg(fc_w + k + 1);
        const float w10 = __ldg(fc_w + 24 + k), w11 = __ldg(fc_w + 24 + k + 1);
        #pragma unroll
        for (int m = 0; m < 4; m++) {
            float e0, e1; unpack2(hown[m][p], e0, e1);
            p0[m] += w00 * e0 + w01 * e1;
            p1[m] += w10 * e0 + w11 * e1;
        }
    }
    #pragma unroll
    for (int off = 1; off < 4; off <<= 1) {
        #pragma unroll
        for (int m = 0; m < 4; m++) {
            p0[m] += __shfl_xor_sync(0xFFFFFFFFu, p0[m], off);
            p1[m] += __shfl_xor_sync(0xFFFFFFFFu, p1[m], off);
        }
    }
    if (q == 0) {
        const float fb0 = __ldg(fc_b + 0), fb1 = __ldg(fc_b + 1);
        #pragma unroll
        for (int m = 0; m < 4; m++) {
            out[2 * (sbase + m) + 0] = p0[m] + fb0;
            out[2 * (sbase + m) + 1] = p1[m] + fb1;
        }
    }
}

extern "C" void kernel_launch(void* const* d_in, const int* in_sizes, int n_in,
                              void* d_out, int out_size)
{
    const float* x    = (const float*)d_in[0];
    const float* W_ih = (const float*)d_in[1];
    const float* b_ih = (const float*)d_in[2];
    const float* W_hh = (const float*)d_in[3];
    const float* b_hh = (const float*)d_in[4];
    const float* fc_w = (const float*)d_in[5];
    const float* fc_b = (const float*)d_in[6];
    float* out = (float*)d_out;

    const int B = out_size / 2;
    const int T = in_sizes[0] / B;

    const int grid = B / 32;   // 1 lane per (cohort, quarter); 8 cohorts per CTA
    trendgru_kernel<<<grid, TPB>>>(x, W_ih, b_ih, W_hh, b_hh, fc_w, fc_b, out, B, T);
}